// round 13
// baseline (speedup 1.0000x reference)
#include <cuda_runtime.h>

#define H 128
#define NNODE 100000
#define EMAX 1600000
#define SCAN_BS 1024
#define SCAN_NB ((NNODE + SCAN_BS - 1) / SCAN_BS)   // 98

#define NB_CONV 782            // (NNODE + 127) / 128
#define NB_GATH 12500          // NNODE / 8
#define NB_COMBO (NB_CONV + NB_GATH)   // 13282
#define COMBO_P 17             // conv every 17th block: 782 convs in 13282

typedef unsigned long long ull;

// ---- scratch (device globals: no allocation allowed) ----
__device__ float g_mean0[NNODE * H];
__device__ float g_mean1[NNODE * H];
__device__ float g_xi1[NNODE * H];
__device__ float g_xu1[NNODE * H];
__device__ float g_xi2[NNODE * H];
__device__ float g_xu2[NNODE * H];
__device__ int g_cnt[2 * NNODE];
__device__ int g_off[2 * (NNODE + 1)];
__device__ int g_cur[2 * NNODE];
__device__ int g_csr[2 * EMAX];
__device__ int g_bsum[2 * SCAN_NB];

// ===========================================================================
// CSR build — merged across both edge types
// ===========================================================================
__global__ void zero_int4_kernel(int4* p, int n4) {
    int i = blockIdx.x * blockDim.x + threadIdx.x;
    if (i < n4) p[i] = make_int4(0, 0, 0, 0);
}

__global__ void count2_kernel(const int* __restrict__ dst0,
                              const int* __restrict__ dst1,
                              int* cnt, int E) {
    int i = blockIdx.x * blockDim.x + threadIdx.x;
    if (i < E) {
        atomicAdd(&cnt[__ldg(&dst0[i])], 1);
    } else if (i < 2 * E) {
        atomicAdd(&cnt[NNODE + __ldg(&dst1[i - E])], 1);
    }
}

__global__ void scan_block2_kernel(const int* __restrict__ cnt, int* off,
                                   int* bsum, int n) {
    __shared__ int sh[SCAN_BS];
    int ty = blockIdx.x / SCAN_NB;
    int blk = blockIdx.x % SCAN_NB;
    const int* c = cnt + ty * n;
    int* o = off + ty * (n + 1);
    int* bs = bsum + ty * SCAN_NB;

    int tid = threadIdx.x;
    int gid = blk * SCAN_BS + tid;
    int v = (gid < n) ? c[gid] : 0;
    sh[tid] = v;
    __syncthreads();
#pragma unroll
    for (int od = 1; od < SCAN_BS; od <<= 1) {
        int t = (tid >= od) ? sh[tid - od] : 0;
        __syncthreads();
        sh[tid] += t;
        __syncthreads();
    }
    if (gid < n) o[gid] = sh[tid] - v;   // exclusive
    if (tid == SCAN_BS - 1) bs[blk] = sh[tid];
}

__global__ void scan_sums2_kernel(int* bsum, int nb) {
    __shared__ int sh[128];
    int* bs = bsum + blockIdx.x * SCAN_NB;
    int tid = threadIdx.x;
    int v = (tid < nb) ? bs[tid] : 0;
    sh[tid] = v;
    __syncthreads();
#pragma unroll
    for (int o = 1; o < 128; o <<= 1) {
        int t = (tid >= o) ? sh[tid - o] : 0;
        __syncthreads();
        sh[tid] += t;
        __syncthreads();
    }
    if (tid < nb) bs[tid] = sh[tid] - v;
}

__global__ void finalize_off2_kernel(int* off, int* cur,
                                     const int* __restrict__ bsum,
                                     int n, int E) {
    int ty = blockIdx.y;
    int* o = off + ty * (n + 1);
    int* cu = cur + ty * n;
    const int* bs = bsum + ty * SCAN_NB;
    int gid = blockIdx.x * blockDim.x + threadIdx.x;
    if (gid < n) {
        int v = o[gid] + bs[gid >> 10];
        o[gid] = v;
        cu[gid] = v;
    }
    if (gid == 0) o[n] = E;
}

__global__ void fill_csr2_kernel(const int* __restrict__ src0,
                                 const int* __restrict__ dst0,
                                 const int* __restrict__ src1,
                                 const int* __restrict__ dst1,
                                 int* cur, int* __restrict__ csr, int E) {
    int ty = blockIdx.y;
    const int* src = ty ? src1 : src0;
    const int* dst = ty ? dst1 : dst0;
    int* cu = cur + ty * NNODE;
    int* cs = csr + ty * EMAX;
    int e = blockIdx.x * blockDim.x + threadIdx.x;
    if (e >= E) return;
    int d = __ldg(&dst[e]);
    int pos = atomicAdd(&cu[d], 1);
    cs[pos] = __ldg(&src[e]);
}

// ===========================================================================
// gather-mean body (one warp per dst row, MLP=4)
// ===========================================================================
__device__ __forceinline__ void gather_body(const float* __restrict__ xsrc,
                                            const int* __restrict__ off,
                                            const int* __restrict__ csr,
                                            float* __restrict__ mean,
                                            int M, int gbid) {
    int row = gbid * 8 + (threadIdx.x >> 5);
    if (row >= M) return;
    int lane = threadIdx.x & 31;
    int beg = __ldg(&off[row]);
    int end = __ldg(&off[row + 1]);
    float4 a0 = make_float4(0.f, 0.f, 0.f, 0.f);
    float4 a1 = make_float4(0.f, 0.f, 0.f, 0.f);
    float4 a2 = make_float4(0.f, 0.f, 0.f, 0.f);
    float4 a3 = make_float4(0.f, 0.f, 0.f, 0.f);
    int j = beg;
    for (; j + 3 < end; j += 4) {
        int s0 = __ldg(&csr[j + 0]);
        int s1 = __ldg(&csr[j + 1]);
        int s2 = __ldg(&csr[j + 2]);
        int s3 = __ldg(&csr[j + 3]);
        float4 v0 = __ldg(((const float4*)(xsrc + (long)s0 * H)) + lane);
        float4 v1 = __ldg(((const float4*)(xsrc + (long)s1 * H)) + lane);
        float4 v2 = __ldg(((const float4*)(xsrc + (long)s2 * H)) + lane);
        float4 v3 = __ldg(((const float4*)(xsrc + (long)s3 * H)) + lane);
        a0.x += v0.x; a0.y += v0.y; a0.z += v0.z; a0.w += v0.w;
        a1.x += v1.x; a1.y += v1.y; a1.z += v1.z; a1.w += v1.w;
        a2.x += v2.x; a2.y += v2.y; a2.z += v2.z; a2.w += v2.w;
        a3.x += v3.x; a3.y += v3.y; a3.z += v3.z; a3.w += v3.w;
    }
    for (; j < end; ++j) {
        int s0 = __ldg(&csr[j]);
        float4 v0 = __ldg(((const float4*)(xsrc + (long)s0 * H)) + lane);
        a0.x += v0.x; a0.y += v0.y; a0.z += v0.z; a0.w += v0.w;
    }
    float inv = 1.0f / fmaxf((float)(end - beg), 1.0f);
    float4 o;
    o.x = ((a0.x + a1.x) + (a2.x + a3.x)) * inv;
    o.y = ((a0.y + a1.y) + (a2.y + a3.y)) * inv;
    o.z = ((a0.z + a1.z) + (a2.z + a3.z)) * inv;
    o.w = ((a0.w + a1.w) + (a2.w + a3.w)) * inv;
    *(((float4*)(mean + (long)row * H)) + lane) = o;
}

// ===========================================================================
__device__ __forceinline__ ull ffma2(ull a, ull b, ull c) {
    ull d;
    asm("fma.rn.f32x2 %0, %1, %2, %3;" : "=l"(d) : "l"(a), "l"(b), "l"(c));
    return d;
}

// Fused SAGEConv GEMM + L2-normalize + relu body (proven 1139.9us version):
// out[m,:] = relu(normalize(mean[m,:] @ Wl + bias + xdst[m,:] @ Wr))
// Tile 128x128, 256 threads, 8x8 per thread, K-chunk 16, register prefetch.
__device__ __forceinline__ void conv_body(const float* __restrict__ meanA,
                                          const float* __restrict__ xdst,
                                          const float* __restrict__ wl,
                                          const float* __restrict__ wr,
                                          const float* __restrict__ bias,
                                          float* __restrict__ out,
                                          int M, int cbid) {
    __shared__ float As2[16][256];   // [k][2*m] duplicated pairs (16 KB)
    __shared__ float Bs[16][128];    // [k][j]                    (8 KB)

    int t = threadIdx.x;
    int tcol = t & 15;
    int trow = t >> 4;
    int m0 = cbid * 128;

    const int a_row0 = (t * 2 + 0) >> 2, a_k40 = (t * 2 + 0) & 3;
    const int a_row1 = (t * 2 + 1) >> 2, a_k41 = (t * 2 + 1) & 3;
    const int b_row0 = (t * 2 + 0) >> 5, b_c40 = (t * 2 + 0) & 31;
    const int b_row1 = (t * 2 + 1) >> 5, b_c41 = (t * 2 + 1) & 31;

    ull acc[8][4];
#pragma unroll
    for (int r = 0; r < 8; ++r)
#pragma unroll
        for (int c = 0; c < 4; ++c) acc[r][c] = 0ull;

    float4 aR0, aR1, bR0, bR1;

    {
        int m;
        m = m0 + a_row0;
        aR0 = (m < M) ? *(const float4*)(meanA + (long)m * H + a_k40 * 4)
                      : make_float4(0.f, 0.f, 0.f, 0.f);
        m = m0 + a_row1;
        aR1 = (m < M) ? *(const float4*)(meanA + (long)m * H + a_k41 * 4)
                      : make_float4(0.f, 0.f, 0.f, 0.f);
        bR0 = *(const float4*)(wl + (long)b_row0 * H + b_c40 * 4);
        bR1 = *(const float4*)(wl + (long)b_row1 * H + b_c41 * 4);
    }

    for (int kc = 0; kc < 16; ++kc) {
        {
            int kk0 = a_k40 * 4;
            *(float2*)&As2[kk0 + 0][2 * a_row0] = make_float2(aR0.x, aR0.x);
            *(float2*)&As2[kk0 + 1][2 * a_row0] = make_float2(aR0.y, aR0.y);
            *(float2*)&As2[kk0 + 2][2 * a_row0] = make_float2(aR0.z, aR0.z);
            *(float2*)&As2[kk0 + 3][2 * a_row0] = make_float2(aR0.w, aR0.w);
            int kk1 = a_k41 * 4;
            *(float2*)&As2[kk1 + 0][2 * a_row1] = make_float2(aR1.x, aR1.x);
            *(float2*)&As2[kk1 + 1][2 * a_row1] = make_float2(aR1.y, aR1.y);
            *(float2*)&As2[kk1 + 2][2 * a_row1] = make_float2(aR1.z, aR1.z);
            *(float2*)&As2[kk1 + 3][2 * a_row1] = make_float2(aR1.w, aR1.w);
            *(float4*)&Bs[b_row0][b_c40 * 4] = bR0;
            *(float4*)&Bs[b_row1][b_c41 * 4] = bR1;
        }
        __syncthreads();

        if (kc < 15) {
            int kn = kc + 1;
            const bool mp = (kn < 8);
            const int kbase = (kn & 7) * 16;
            const float* asrc = mp ? meanA : xdst;
            const float* bsrc = mp ? wl : wr;
            int m;
            m = m0 + a_row0;
            aR0 = (m < M) ? *(const float4*)(asrc + (long)m * H + kbase + a_k40 * 4)
                          : make_float4(0.f, 0.f, 0.f, 0.f);
            m = m0 + a_row1;
            aR1 = (m < M) ? *(const float4*)(asrc + (long)m * H + kbase + a_k41 * 4)
                          : make_float4(0.f, 0.f, 0.f, 0.f);
            bR0 = *(const float4*)(bsrc + (long)(kbase + b_row0) * H + b_c40 * 4);
            bR1 = *(const float4*)(bsrc + (long)(kbase + b_row1) * H + b_c41 * 4);
        }

#pragma unroll
        for (int k = 0; k < 16; ++k) {
            const ulonglong2* ap = (const ulonglong2*)&As2[k][trow * 16];
            ulonglong2 A0 = ap[0];
            ulonglong2 A1 = ap[1];
            ulonglong2 A2 = ap[2];
            ulonglong2 A3 = ap[3];
            const ulonglong2* bp = (const ulonglong2*)&Bs[k][tcol * 8];
            ulonglong2 B0 = bp[0];
            ulonglong2 B1 = bp[1];
            ull a[8] = {A0.x, A0.y, A1.x, A1.y, A2.x, A2.y, A3.x, A3.y};
#pragma unroll
            for (int r = 0; r < 8; ++r) {
                acc[r][0] = ffma2(a[r], B0.x, acc[r][0]);
                acc[r][1] = ffma2(a[r], B0.y, acc[r][1]);
                acc[r][2] = ffma2(a[r], B1.x, acc[r][2]);
                acc[r][3] = ffma2(a[r], B1.y, acc[r][3]);
            }
        }
        __syncthreads();
    }

    // ---- epilogue: + bias, row L2-norm (block-local), relu, store ----
    float bv[8];
    {
        float4 f0 = *(const float4*)(bias + tcol * 8);
        float4 f1 = *(const float4*)(bias + tcol * 8 + 4);
        bv[0] = f0.x; bv[1] = f0.y; bv[2] = f0.z; bv[3] = f0.w;
        bv[4] = f1.x; bv[5] = f1.y; bv[6] = f1.z; bv[7] = f1.w;
    }
    float vals[8][8];
#pragma unroll
    for (int r = 0; r < 8; ++r)
#pragma unroll
        for (int c2 = 0; c2 < 4; ++c2) {
            ull p = acc[r][c2];
            vals[r][2 * c2 + 0] = __uint_as_float((unsigned)(p & 0xffffffffull)) + bv[2 * c2 + 0];
            vals[r][2 * c2 + 1] = __uint_as_float((unsigned)(p >> 32)) + bv[2 * c2 + 1];
        }

    float* red = &As2[0][0];
#pragma unroll
    for (int r = 0; r < 8; ++r) {
        float p = 0.f;
#pragma unroll
        for (int c = 0; c < 8; ++c) p = fmaf(vals[r][c], vals[r][c], p);
        red[(trow * 8 + r) * 16 + tcol] = p;
    }
    __syncthreads();

#pragma unroll
    for (int r = 0; r < 8; ++r) {
        int m = m0 + trow * 8 + r;
        const float4* q = (const float4*)&red[(trow * 8 + r) * 16];
        float4 s0 = q[0], s1 = q[1], s2 = q[2], s3 = q[3];
        float s = ((s0.x + s0.y) + (s0.z + s0.w)) + ((s1.x + s1.y) + (s1.z + s1.w))
                + ((s2.x + s2.y) + (s2.z + s2.w)) + ((s3.x + s3.y) + (s3.z + s3.w));
        float scale = 1.0f / fmaxf(sqrtf(s), 1e-12f);
        if (m < M) {
            int j = tcol * 8;
            float4 o;
            o.x = fmaxf(vals[r][0] * scale, 0.f);
            o.y = fmaxf(vals[r][1] * scale, 0.f);
            o.z = fmaxf(vals[r][2] * scale, 0.f);
            o.w = fmaxf(vals[r][3] * scale, 0.f);
            *(float4*)(out + (long)m * H + j) = o;
            o.x = fmaxf(vals[r][4] * scale, 0.f);
            o.y = fmaxf(vals[r][5] * scale, 0.f);
            o.z = fmaxf(vals[r][6] * scale, 0.f);
            o.w = fmaxf(vals[r][7] * scale, 0.f);
            *(float4*)(out + (long)m * H + j + 4) = o;
        }
    }
}

// ===========================================================================
// kernels: standalone gather, standalone conv, and the mixed combo
// ===========================================================================
__global__ void __launch_bounds__(256, 2)
gather_mean_kernel(const float* __restrict__ xsrc,
                   const int* __restrict__ off,
                   const int* __restrict__ csr,
                   float* __restrict__ mean, int M) {
    gather_body(xsrc, off, csr, mean, M, blockIdx.x);
}

__global__ void __launch_bounds__(256, 2)
conv_gemm_kernel(const float* __restrict__ meanA,
                 const float* __restrict__ xdst,
                 const float* __restrict__ wl, const float* __restrict__ wr,
                 const float* __restrict__ bias,
                 float* __restrict__ out, int M) {
    conv_body(meanA, xdst, wl, wr, bias, out, M, blockIdx.x);
}

// mixed launch: conv of the current pass runs concurrently with the gather
// of the NEXT pass (independent data). conv blocks at bid % 17 == 0.
__global__ void __launch_bounds__(256, 2)
combo_kernel(const float* __restrict__ gx, const int* __restrict__ goff,
             const int* __restrict__ gcsr, float* __restrict__ gmean, int gM,
             const float* __restrict__ cmean, const float* __restrict__ cxdst,
             const float* __restrict__ cwl, const float* __restrict__ cwr,
             const float* __restrict__ cbias, float* __restrict__ cout,
             int cM) {
    int bid = blockIdx.x;
    if (bid % COMBO_P == 0) {
        int cbid = bid / COMBO_P;
        if (cbid < NB_CONV)
            conv_body(cmean, cxdst, cwl, cwr, cbias, cout, cM, cbid);
    } else {
        int gbid = bid - (bid + COMBO_P - 1) / COMBO_P;
        if (gbid < NB_GATH)
            gather_body(gx, goff, gcsr, gmean, gM, gbid);
    }
}

// one warp per labeled edge: dot(xu2[src], xi2[dst])
__global__ void classifier_kernel(const float* __restrict__ xu,
                                  const float* __restrict__ xi,
                                  const int* __restrict__ lsrc,
                                  const int* __restrict__ ldst,
                                  float* __restrict__ out, int L) {
    int e = blockIdx.x * 8 + (threadIdx.x >> 5);
    if (e >= L) return;
    int lane = threadIdx.x & 31;
    int s = __ldg(&lsrc[e]);
    int d = __ldg(&ldst[e]);
    float4 a = __ldg(((const float4*)(xu + (long)s * H)) + lane);
    float4 b = __ldg(((const float4*)(xi + (long)d * H)) + lane);
    float v = a.x * b.x + a.y * b.y + a.z * b.z + a.w * b.w;
#pragma unroll
    for (int o = 16; o; o >>= 1) v += __shfl_xor_sync(0xffffffffu, v, o);
    if (lane == 0) out[e] = v;
}

// ===========================================================================
extern "C" void kernel_launch(void* const* d_in, const int* in_sizes, int n_in,
                              void* d_out, int out_size) {
    const float* emb_u = (const float*)d_in[0];
    const float* emb_i = (const float*)d_in[1];
    const int* er  = (const int*)d_in[2];   // edge_rates [2, E]
    const int* erv = (const int*)d_in[3];   // edge_rev   [2, E]
    const int* lbl = (const int*)d_in[4];   // edge_label_index [2, L]
    const float* w1l_rates = (const float*)d_in[5];
    const float* w1r_rates = (const float*)d_in[6];
    const float* w1l_rev   = (const float*)d_in[7];
    const float* w1r_rev   = (const float*)d_in[8];
    const float* w2l_rates = (const float*)d_in[9];
    const float* w2r_rates = (const float*)d_in[10];
    const float* w2l_rev   = (const float*)d_in[11];
    const float* w2r_rev   = (const float*)d_in[12];
    const float* b1_rates  = (const float*)d_in[13];
    const float* b1_rev    = (const float*)d_in[14];
    const float* b2_rates  = (const float*)d_in[15];
    const float* b2_rev    = (const float*)d_in[16];
    float* out = (float*)d_out;

    const int E = in_sizes[2] / 2;
    const int L = in_sizes[4] / 2;

    float *mean0, *mean1, *xi1, *xu1, *xi2, *xu2;
    int *cnt, *off, *cur, *csr, *bsum;
    cudaGetSymbolAddress((void**)&mean0, g_mean0);
    cudaGetSymbolAddress((void**)&mean1, g_mean1);
    cudaGetSymbolAddress((void**)&xi1,  g_xi1);
    cudaGetSymbolAddress((void**)&xu1,  g_xu1);
    cudaGetSymbolAddress((void**)&xi2,  g_xi2);
    cudaGetSymbolAddress((void**)&xu2,  g_xu2);
    cudaGetSymbolAddress((void**)&cnt,  g_cnt);
    cudaGetSymbolAddress((void**)&off,  g_off);
    cudaGetSymbolAddress((void**)&cur,  g_cur);
    cudaGetSymbolAddress((void**)&csr,  g_csr);
    cudaGetSymbolAddress((void**)&bsum, g_bsum);

    // index 0 = rates (dst = items), index 1 = rev (dst = users)
    int* off_t[2] = {off, off + (NNODE + 1)};
    int* csr_t[2] = {csr, csr + EMAX};

    const int NB_E  = (E + 255) / 256;
    const int NB_2E = (2 * E + 255) / 256;
    const int NB_L  = (L + 7) / 8;
    const int NB_N  = (NNODE + 255) / 256;

    // ---- CSR build, both edge types merged ----
    zero_int4_kernel<<<(2 * NNODE / 4 + 255) / 256, 256>>>((int4*)cnt, 2 * NNODE / 4);
    count2_kernel<<<NB_2E, 256>>>(er + E, erv + E, cnt, E);
    scan_block2_kernel<<<2 * SCAN_NB, SCAN_BS>>>(cnt, off, bsum, NNODE);
    scan_sums2_kernel<<<2, 128>>>(bsum, SCAN_NB);
    {
        dim3 g(NB_N, 2);
        finalize_off2_kernel<<<g, 256>>>(off, cur, bsum, NNODE, E);
    }
    {
        dim3 g(NB_E, 2);
        fill_csr2_kernel<<<g, 256>>>(er, er + E, erv, erv + E, cur, csr, E);
    }

    // Pass A: items L1   mean0 = gather(csr0, emb_u); xi1 = conv(mean0, emb_i, W1rates)
    // Pass B: users L1   mean1 = gather(csr1, emb_i); xu1 = conv(mean1, emb_u, W1rev)
    // Pass C: users L2   mean0 = gather(csr1, xi1);   xu2 = conv(mean0, xu1, W2rev)
    // Pass D: items L2   mean1 = gather(csr0, xu1);   xi2 = conv(mean1, xi1, W2rates)

    // 1) gather A
    gather_mean_kernel<<<NB_GATH, 256>>>(emb_u, off_t[0], csr_t[0], mean0, NNODE);

    // 2) conv A  ||  gather B
    combo_kernel<<<NB_COMBO, 256>>>(
        emb_i, off_t[1], csr_t[1], mean1, NNODE,
        mean0, emb_i, w1l_rates, w1r_rates, b1_rates, xi1, NNODE);

    // 3) conv B  ||  gather C   (gather C reads xi1 from launch 2)
    combo_kernel<<<NB_COMBO, 256>>>(
        xi1, off_t[1], csr_t[1], mean0, NNODE,
        mean1, emb_u, w1l_rev, w1r_rev, b1_rev, xu1, NNODE);

    // 4) conv C  ||  gather D   (both read xu1 from launch 3)
    combo_kernel<<<NB_COMBO, 256>>>(
        xu1, off_t[0], csr_t[0], mean1, NNODE,
        mean0, xu1, w2l_rev, w2r_rev, b2_rev, xu2, NNODE);

    // 5) conv D
    conv_gemm_kernel<<<NB_CONV, 256>>>(mean1, xi1, w2l_rates, w2r_rates,
                                       b2_rates, xi2, NNODE);

    // 6) classifier
    classifier_kernel<<<NB_L, 256>>>(xu2, xi2, lbl, lbl + L, out, L);
}

// round 14
// speedup vs baseline: 1.0091x; 1.0091x over previous
#include <cuda_runtime.h>

#define H 128
#define NNODE 100000
#define EMAX 1600000
#define SCAN_BS 1024
#define SCAN_NB ((NNODE + SCAN_BS - 1) / SCAN_BS)   // 98

typedef unsigned long long ull;

// ---- scratch (device globals: no allocation allowed) ----
__device__ float g_mean0[NNODE * H];
__device__ float g_mean1[NNODE * H];
__device__ float g_xi1[NNODE * H];
__device__ float g_xu1[NNODE * H];
__device__ float g_xi2[NNODE * H];
__device__ float g_xu2[NNODE * H];
__device__ int g_cnt[2][NNODE];
__device__ int g_off[2][NNODE + 1];
__device__ int g_cur[2][NNODE];
__device__ int g_csr[2][EMAX];
__device__ int g_bsum[2][SCAN_NB];

// parameter bundles for batched (grid.y = 2) launches
struct GatherPair {
    const float* x[2];
    const int* off[2];
    const int* csr[2];
    float* mean[2];
};
struct ConvPair {
    const float* mean[2];
    const float* xdst[2];
    const float* wl[2];
    const float* wr[2];
    const float* bias[2];
    float* out[2];
};

// ===========================================================================
// CSR build (split per edge type — proven 1139.9us configuration)
// ===========================================================================
__global__ void zero_int4_kernel(int4* p, int n4) {
    int i = blockIdx.x * blockDim.x + threadIdx.x;
    if (i < n4) p[i] = make_int4(0, 0, 0, 0);
}

__global__ void count_kernel(const int* __restrict__ dst, int* cnt, int E) {
    int i = blockIdx.x * blockDim.x + threadIdx.x;
    if (i < E) atomicAdd(&cnt[dst[i]], 1);
}

__global__ void scan_block_kernel(const int* __restrict__ cnt, int* off,
                                  int* bsum, int n) {
    __shared__ int sh[SCAN_BS];
    int tid = threadIdx.x;
    int gid = blockIdx.x * SCAN_BS + tid;
    int v = (gid < n) ? cnt[gid] : 0;
    sh[tid] = v;
    __syncthreads();
#pragma unroll
    for (int o = 1; o < SCAN_BS; o <<= 1) {
        int t = (tid >= o) ? sh[tid - o] : 0;
        __syncthreads();
        sh[tid] += t;
        __syncthreads();
    }
    if (gid < n) off[gid] = sh[tid] - v;   // exclusive
    if (tid == SCAN_BS - 1) bsum[blockIdx.x] = sh[tid];
}

__global__ void scan_sums_kernel(int* bsum, int nb) {
    __shared__ int sh[128];
    int tid = threadIdx.x;
    int v = (tid < nb) ? bsum[tid] : 0;
    sh[tid] = v;
    __syncthreads();
#pragma unroll
    for (int o = 1; o < 128; o <<= 1) {
        int t = (tid >= o) ? sh[tid - o] : 0;
        __syncthreads();
        sh[tid] += t;
        __syncthreads();
    }
    if (tid < nb) bsum[tid] = sh[tid] - v;
}

__global__ void finalize_off_kernel(int* off, int* cur,
                                    const int* __restrict__ bsum, int n, int E) {
    int gid = blockIdx.x * blockDim.x + threadIdx.x;
    if (gid < n) {
        int o = off[gid] + bsum[gid >> 10];
        off[gid] = o;
        cur[gid] = o;
    }
    if (gid == 0) off[n] = E;
}

__global__ void fill_csr_kernel(const int* __restrict__ src,
                                const int* __restrict__ dst,
                                int* cur, int* __restrict__ csr, int E) {
    int e = blockIdx.x * blockDim.x + threadIdx.x;
    if (e >= E) return;
    int d = __ldg(&dst[e]);
    int pos = atomicAdd(&cur[d], 1);
    csr[pos] = __ldg(&src[e]);
}

// ===========================================================================
// gather-mean, batched over 2 independent passes via blockIdx.y
// (one warp per dst row, MLP=4 — body identical to the 1139.9us version)
// ===========================================================================
__global__ void __launch_bounds__(256, 2)
gather_pair_kernel(GatherPair gp, int M) {
    int p = blockIdx.y;
    const float* __restrict__ xsrc = gp.x[p];
    const int* __restrict__ off = gp.off[p];
    const int* __restrict__ csr = gp.csr[p];
    float* __restrict__ mean = gp.mean[p];

    int row = blockIdx.x * 8 + (threadIdx.x >> 5);
    if (row >= M) return;
    int lane = threadIdx.x & 31;
    int beg = __ldg(&off[row]);
    int end = __ldg(&off[row + 1]);
    float4 a0 = make_float4(0.f, 0.f, 0.f, 0.f);
    float4 a1 = make_float4(0.f, 0.f, 0.f, 0.f);
    float4 a2 = make_float4(0.f, 0.f, 0.f, 0.f);
    float4 a3 = make_float4(0.f, 0.f, 0.f, 0.f);
    int j = beg;
    for (; j + 3 < end; j += 4) {
        int s0 = __ldg(&csr[j + 0]);
        int s1 = __ldg(&csr[j + 1]);
        int s2 = __ldg(&csr[j + 2]);
        int s3 = __ldg(&csr[j + 3]);
        float4 v0 = __ldg(((const float4*)(xsrc + (long)s0 * H)) + lane);
        float4 v1 = __ldg(((const float4*)(xsrc + (long)s1 * H)) + lane);
        float4 v2 = __ldg(((const float4*)(xsrc + (long)s2 * H)) + lane);
        float4 v3 = __ldg(((const float4*)(xsrc + (long)s3 * H)) + lane);
        a0.x += v0.x; a0.y += v0.y; a0.z += v0.z; a0.w += v0.w;
        a1.x += v1.x; a1.y += v1.y; a1.z += v1.z; a1.w += v1.w;
        a2.x += v2.x; a2.y += v2.y; a2.z += v2.z; a2.w += v2.w;
        a3.x += v3.x; a3.y += v3.y; a3.z += v3.z; a3.w += v3.w;
    }
    for (; j < end; ++j) {
        int s0 = __ldg(&csr[j]);
        float4 v0 = __ldg(((const float4*)(xsrc + (long)s0 * H)) + lane);
        a0.x += v0.x; a0.y += v0.y; a0.z += v0.z; a0.w += v0.w;
    }
    float inv = 1.0f / fmaxf((float)(end - beg), 1.0f);
    float4 o;
    o.x = ((a0.x + a1.x) + (a2.x + a3.x)) * inv;
    o.y = ((a0.y + a1.y) + (a2.y + a3.y)) * inv;
    o.z = ((a0.z + a1.z) + (a2.z + a3.z)) * inv;
    o.w = ((a0.w + a1.w) + (a2.w + a3.w)) * inv;
    *(((float4*)(mean + (long)row * H)) + lane) = o;
}

// ===========================================================================
__device__ __forceinline__ ull ffma2(ull a, ull b, ull c) {
    ull d;
    asm("fma.rn.f32x2 %0, %1, %2, %3;" : "=l"(d) : "l"(a), "l"(b), "l"(c));
    return d;
}

// Fused SAGEConv GEMM + L2-normalize + relu, batched over 2 passes via
// blockIdx.y. Body identical to the proven 1139.9us kernel.
__global__ void __launch_bounds__(256, 2)
conv_pair_kernel(ConvPair cp, int M) {
    __shared__ float As2[16][256];   // [k][2*m] duplicated pairs (16 KB)
    __shared__ float Bs[16][128];    // [k][j]                    (8 KB)

    int p = blockIdx.y;
    const float* __restrict__ meanA = cp.mean[p];
    const float* __restrict__ xdst = cp.xdst[p];
    const float* __restrict__ wl = cp.wl[p];
    const float* __restrict__ wr = cp.wr[p];
    const float* __restrict__ bias = cp.bias[p];
    float* __restrict__ out = cp.out[p];

    int t = threadIdx.x;
    int tcol = t & 15;   // 16 col-groups * 8 cols
    int trow = t >> 4;   // 16 row-groups * 8 rows
    int m0 = blockIdx.x * 128;

    const int a_row0 = (t * 2 + 0) >> 2, a_k40 = (t * 2 + 0) & 3;
    const int a_row1 = (t * 2 + 1) >> 2, a_k41 = (t * 2 + 1) & 3;
    const int b_row0 = (t * 2 + 0) >> 5, b_c40 = (t * 2 + 0) & 31;
    const int b_row1 = (t * 2 + 1) >> 5, b_c41 = (t * 2 + 1) & 31;

    ull acc[8][4];
#pragma unroll
    for (int r = 0; r < 8; ++r)
#pragma unroll
        for (int c = 0; c < 4; ++c) acc[r][c] = 0ull;

    float4 aR0, aR1, bR0, bR1;

    // prefetch chunk 0
    {
        int m;
        m = m0 + a_row0;
        aR0 = (m < M) ? *(const float4*)(meanA + (long)m * H + a_k40 * 4)
                      : make_float4(0.f, 0.f, 0.f, 0.f);
        m = m0 + a_row1;
        aR1 = (m < M) ? *(const float4*)(meanA + (long)m * H + a_k41 * 4)
                      : make_float4(0.f, 0.f, 0.f, 0.f);
        bR0 = *(const float4*)(wl + (long)b_row0 * H + b_c40 * 4);
        bR1 = *(const float4*)(wl + (long)b_row1 * H + b_c41 * 4);
    }

    for (int kc = 0; kc < 16; ++kc) {
        // store current chunk to smem (A duplicated for packed broadcast)
        {
            int kk0 = a_k40 * 4;
            *(float2*)&As2[kk0 + 0][2 * a_row0] = make_float2(aR0.x, aR0.x);
            *(float2*)&As2[kk0 + 1][2 * a_row0] = make_float2(aR0.y, aR0.y);
            *(float2*)&As2[kk0 + 2][2 * a_row0] = make_float2(aR0.z, aR0.z);
            *(float2*)&As2[kk0 + 3][2 * a_row0] = make_float2(aR0.w, aR0.w);
            int kk1 = a_k41 * 4;
            *(float2*)&As2[kk1 + 0][2 * a_row1] = make_float2(aR1.x, aR1.x);
            *(float2*)&As2[kk1 + 1][2 * a_row1] = make_float2(aR1.y, aR1.y);
            *(float2*)&As2[kk1 + 2][2 * a_row1] = make_float2(aR1.z, aR1.z);
            *(float2*)&As2[kk1 + 3][2 * a_row1] = make_float2(aR1.w, aR1.w);
            *(float4*)&Bs[b_row0][b_c40 * 4] = bR0;
            *(float4*)&Bs[b_row1][b_c41 * 4] = bR1;
        }
        __syncthreads();

        // prefetch next chunk (overlaps the FFMA loop below)
        if (kc < 15) {
            int kn = kc + 1;
            const bool mp = (kn < 8);
            const int kbase = (kn & 7) * 16;
            const float* asrc = mp ? meanA : xdst;
            const float* bsrc = mp ? wl : wr;
            int m;
            m = m0 + a_row0;
            aR0 = (m < M) ? *(const float4*)(asrc + (long)m * H + kbase + a_k40 * 4)
                          : make_float4(0.f, 0.f, 0.f, 0.f);
            m = m0 + a_row1;
            aR1 = (m < M) ? *(const float4*)(asrc + (long)m * H + kbase + a_k41 * 4)
                          : make_float4(0.f, 0.f, 0.f, 0.f);
            bR0 = *(const float4*)(bsrc + (long)(kbase + b_row0) * H + b_c40 * 4);
            bR1 = *(const float4*)(bsrc + (long)(kbase + b_row1) * H + b_c41 * 4);
        }

#pragma unroll
        for (int k = 0; k < 16; ++k) {
            const ulonglong2* ap = (const ulonglong2*)&As2[k][trow * 16];
            ulonglong2 A0 = ap[0];
            ulonglong2 A1 = ap[1];
            ulonglong2 A2 = ap[2];
            ulonglong2 A3 = ap[3];
            const ulonglong2* bp = (const ulonglong2*)&Bs[k][tcol * 8];
            ulonglong2 B0 = bp[0];
            ulonglong2 B1 = bp[1];
            ull a[8] = {A0.x, A0.y, A1.x, A1.y, A2.x, A2.y, A3.x, A3.y};
#pragma unroll
            for (int r = 0; r < 8; ++r) {
                acc[r][0] = ffma2(a[r], B0.x, acc[r][0]);
                acc[r][1] = ffma2(a[r], B0.y, acc[r][1]);
                acc[r][2] = ffma2(a[r], B1.x, acc[r][2]);
                acc[r][3] = ffma2(a[r], B1.y, acc[r][3]);
            }
        }
        __syncthreads();
    }

    // ---- epilogue: + bias, row L2-norm (block-local), relu, store ----
    float bv[8];
    {
        float4 f0 = *(const float4*)(bias + tcol * 8);
        float4 f1 = *(const float4*)(bias + tcol * 8 + 4);
        bv[0] = f0.x; bv[1] = f0.y; bv[2] = f0.z; bv[3] = f0.w;
        bv[4] = f1.x; bv[5] = f1.y; bv[6] = f1.z; bv[7] = f1.w;
    }
    float vals[8][8];
#pragma unroll
    for (int r = 0; r < 8; ++r)
#pragma unroll
        for (int c2 = 0; c2 < 4; ++c2) {
            ull p2 = acc[r][c2];
            vals[r][2 * c2 + 0] = __uint_as_float((unsigned)(p2 & 0xffffffffull)) + bv[2 * c2 + 0];
            vals[r][2 * c2 + 1] = __uint_as_float((unsigned)(p2 >> 32)) + bv[2 * c2 + 1];
        }

    float* red = &As2[0][0];
#pragma unroll
    for (int r = 0; r < 8; ++r) {
        float pp = 0.f;
#pragma unroll
        for (int c = 0; c < 8; ++c) pp = fmaf(vals[r][c], vals[r][c], pp);
        red[(trow * 8 + r) * 16 + tcol] = pp;
    }
    __syncthreads();

#pragma unroll
    for (int r = 0; r < 8; ++r) {
        int m = m0 + trow * 8 + r;
        const float4* q = (const float4*)&red[(trow * 8 + r) * 16];
        float4 s0 = q[0], s1 = q[1], s2 = q[2], s3 = q[3];
        float s = ((s0.x + s0.y) + (s0.z + s0.w)) + ((s1.x + s1.y) + (s1.z + s1.w))
                + ((s2.x + s2.y) + (s2.z + s2.w)) + ((s3.x + s3.y) + (s3.z + s3.w));
        float scale = 1.0f / fmaxf(sqrtf(s), 1e-12f);
        if (m < M) {
            int j = tcol * 8;
            float4 o;
            o.x = fmaxf(vals[r][0] * scale, 0.f);
            o.y = fmaxf(vals[r][1] * scale, 0.f);
            o.z = fmaxf(vals[r][2] * scale, 0.f);
            o.w = fmaxf(vals[r][3] * scale, 0.f);
            *(float4*)(out + (long)m * H + j) = o;
            o.x = fmaxf(vals[r][4] * scale, 0.f);
            o.y = fmaxf(vals[r][5] * scale, 0.f);
            o.z = fmaxf(vals[r][6] * scale, 0.f);
            o.w = fmaxf(vals[r][7] * scale, 0.f);
            *(float4*)(out + (long)m * H + j + 4) = o;
        }
    }
}

// one warp per labeled edge: dot(xu2[src], xi2[dst])
__global__ void classifier_kernel(const float* __restrict__ xu,
                                  const float* __restrict__ xi,
                                  const int* __restrict__ lsrc,
                                  const int* __restrict__ ldst,
                                  float* __restrict__ out, int L) {
    int e = blockIdx.x * 8 + (threadIdx.x >> 5);
    if (e >= L) return;
    int lane = threadIdx.x & 31;
    int s = __ldg(&lsrc[e]);
    int d = __ldg(&ldst[e]);
    float4 a = __ldg(((const float4*)(xu + (long)s * H)) + lane);
    float4 b = __ldg(((const float4*)(xi + (long)d * H)) + lane);
    float v = a.x * b.x + a.y * b.y + a.z * b.z + a.w * b.w;
#pragma unroll
    for (int o = 16; o; o >>= 1) v += __shfl_xor_sync(0xffffffffu, v, o);
    if (lane == 0) out[e] = v;
}

// ===========================================================================
extern "C" void kernel_launch(void* const* d_in, const int* in_sizes, int n_in,
                              void* d_out, int out_size) {
    const float* emb_u = (const float*)d_in[0];
    const float* emb_i = (const float*)d_in[1];
    const int* er  = (const int*)d_in[2];   // edge_rates [2, E]
    const int* erv = (const int*)d_in[3];   // edge_rev   [2, E]
    const int* lbl = (const int*)d_in[4];   // edge_label_index [2, L]
    const float* w1l_rates = (const float*)d_in[5];
    const float* w1r_rates = (const float*)d_in[6];
    const float* w1l_rev   = (const float*)d_in[7];
    const float* w1r_rev   = (const float*)d_in[8];
    const float* w2l_rates = (const float*)d_in[9];
    const float* w2r_rates = (const float*)d_in[10];
    const float* w2l_rev   = (const float*)d_in[11];
    const float* w2r_rev   = (const float*)d_in[12];
    const float* b1_rates  = (const float*)d_in[13];
    const float* b1_rev    = (const float*)d_in[14];
    const float* b2_rates  = (const float*)d_in[15];
    const float* b2_rev    = (const float*)d_in[16];
    float* out = (float*)d_out;

    const int E = in_sizes[2] / 2;
    const int L = in_sizes[4] / 2;

    float *mean0, *mean1, *xi1, *xu1, *xi2, *xu2;
    int *cnt, *off, *cur, *csr, *bsum;
    cudaGetSymbolAddress((void**)&mean0, g_mean0);
    cudaGetSymbolAddress((void**)&mean1, g_mean1);
    cudaGetSymbolAddress((void**)&xi1,  g_xi1);
    cudaGetSymbolAddress((void**)&xu1,  g_xu1);
    cudaGetSymbolAddress((void**)&xi2,  g_xi2);
    cudaGetSymbolAddress((void**)&xu2,  g_xu2);
    cudaGetSymbolAddress((void**)&cnt,  g_cnt);
    cudaGetSymbolAddress((void**)&off,  g_off);
    cudaGetSymbolAddress((void**)&cur,  g_cur);
    cudaGetSymbolAddress((void**)&csr,  g_csr);
    cudaGetSymbolAddress((void**)&bsum, g_bsum);

    // index 0 = rates (dst = items), index 1 = rev (dst = users)
    int* cnt_t[2]  = {cnt, cnt + NNODE};
    int* off_t[2]  = {off, off + (NNODE + 1)};
    int* cur_t[2]  = {cur, cur + NNODE};
    int* csr_t[2]  = {csr, csr + EMAX};
    int* bsum_t[2] = {bsum, bsum + SCAN_NB};
    const int* src_t[2] = {er, erv};
    const int* dst_t[2] = {er + E, erv + E};

    const int NB_E    = (E + 255) / 256;
    const int NB_ROWS = (NNODE + 7) / 8;
    const int NB_L    = (L + 7) / 8;
    const int NB_N    = (NNODE + 255) / 256;
    const dim3 G_GATH((unsigned)NB_ROWS, 2);
    const dim3 G_CONV((unsigned)((NNODE + 127) / 128), 2);

    // ---- CSR build (split per type — proven configuration) ----
    for (int ty = 0; ty < 2; ++ty) {
        zero_int4_kernel<<<(NNODE / 4 + 255) / 256, 256>>>((int4*)cnt_t[ty], NNODE / 4);
        count_kernel<<<NB_E, 256>>>(dst_t[ty], cnt_t[ty], E);
        scan_block_kernel<<<SCAN_NB, SCAN_BS>>>(cnt_t[ty], off_t[ty], bsum_t[ty], NNODE);
        scan_sums_kernel<<<1, 128>>>(bsum_t[ty], SCAN_NB);
        finalize_off_kernel<<<NB_N, 256>>>(off_t[ty], cur_t[ty], bsum_t[ty], NNODE, E);
        fill_csr_kernel<<<NB_E, 256>>>(src_t[ty], dst_t[ty], cur_t[ty], csr_t[ty], E);
    }

    // ---- layer 1: both passes batched ----
    // A: mean0 = gather(csr0, emb_u);  B: mean1 = gather(csr1, emb_i)
    {
        GatherPair gp;
        gp.x[0] = emb_u; gp.off[0] = off_t[0]; gp.csr[0] = csr_t[0]; gp.mean[0] = mean0;
        gp.x[1] = emb_i; gp.off[1] = off_t[1]; gp.csr[1] = csr_t[1]; gp.mean[1] = mean1;
        gather_pair_kernel<<<G_GATH, 256>>>(gp, NNODE);
    }
    // xi1 = conv(mean0, emb_i, W1rates);  xu1 = conv(mean1, emb_u, W1rev)
    {
        ConvPair cp;
        cp.mean[0] = mean0; cp.xdst[0] = emb_i; cp.wl[0] = w1l_rates;
        cp.wr[0] = w1r_rates; cp.bias[0] = b1_rates; cp.out[0] = xi1;
        cp.mean[1] = mean1; cp.xdst[1] = emb_u; cp.wl[1] = w1l_rev;
        cp.wr[1] = w1r_rev; cp.bias[1] = b1_rev; cp.out[1] = xu1;
        conv_pair_kernel<<<G_CONV, 256>>>(cp, NNODE);
    }

    // ---- layer 2: both passes batched ----
    // C: mean0 = gather(csr0, xu1);  D: mean1 = gather(csr1, xi1)
    {
        GatherPair gp;
        gp.x[0] = xu1; gp.off[0] = off_t[0]; gp.csr[0] = csr_t[0]; gp.mean[0] = mean0;
        gp.x[1] = xi1; gp.off[1] = off_t[1]; gp.csr[1] = csr_t[1]; gp.mean[1] = mean1;
        gather_pair_kernel<<<G_GATH, 256>>>(gp, NNODE);
    }
    // xi2 = conv(mean0, xi1, W2rates);  xu2 = conv(mean1, xu1, W2rev)
    {
        ConvPair cp;
        cp.mean[0] = mean0; cp.xdst[0] = xi1; cp.wl[0] = w2l_rates;
        cp.wr[0] = w2r_rates; cp.bias[0] = b2_rates; cp.out[0] = xi2;
        cp.mean[1] = mean1; cp.xdst[1] = xu1; cp.wl[1] = w2l_rev;
        cp.wr[1] = w2r_rev; cp.bias[1] = b2_rev; cp.out[1] = xu2;
        conv_pair_kernel<<<G_CONV, 256>>>(cp, NNODE);
    }

    // ---- classifier ----
    classifier_kernel<<<NB_L, 256>>>(xu2, xi2, lbl, lbl + L, out, L);
}

// round 15
// speedup vs baseline: 1.0306x; 1.0213x over previous
#include <cuda_runtime.h>

#define H 128
#define NNODE 100000
#define EMAX 1600000
#define SCAN_BS 1024
#define SCAN_NB ((NNODE + SCAN_BS - 1) / SCAN_BS)   // 98

typedef unsigned long long ull;

// ---- scratch (device globals: no allocation allowed) ----
__device__ float g_mean[NNODE * H];
__device__ float g_xi1[NNODE * H];
__device__ float g_xu1[NNODE * H];
__device__ float g_xi2[NNODE * H];
__device__ float g_xu2[NNODE * H];
__device__ int g_cnt[2][NNODE];
__device__ int g_off[2][NNODE + 1];
__device__ int g_cur[2][NNODE];
__device__ int g_csr[2][EMAX];
__device__ int g_bsum[2][SCAN_NB];

// ---------------------------------------------------------------------------
__global__ void zero_int4_kernel(int4* p, int n4) {
    int i = blockIdx.x * blockDim.x + threadIdx.x;
    if (i < n4) p[i] = make_int4(0, 0, 0, 0);
}

__global__ void count_kernel(const int* __restrict__ dst, int* cnt, int E) {
    int i = blockIdx.x * blockDim.x + threadIdx.x;
    if (i < E) atomicAdd(&cnt[dst[i]], 1);
}

// phase 1: per-block exclusive scan, emit block sums
__global__ void scan_block_kernel(const int* __restrict__ cnt, int* off,
                                  int* bsum, int n) {
    __shared__ int sh[SCAN_BS];
    int tid = threadIdx.x;
    int gid = blockIdx.x * SCAN_BS + tid;
    int v = (gid < n) ? cnt[gid] : 0;
    sh[tid] = v;
    __syncthreads();
#pragma unroll
    for (int o = 1; o < SCAN_BS; o <<= 1) {
        int t = (tid >= o) ? sh[tid - o] : 0;
        __syncthreads();
        sh[tid] += t;
        __syncthreads();
    }
    if (gid < n) off[gid] = sh[tid] - v;   // exclusive
    if (tid == SCAN_BS - 1) bsum[blockIdx.x] = sh[tid];
}

// phase 2: single-block exclusive scan of block sums (nb <= 128)
__global__ void scan_sums_kernel(int* bsum, int nb) {
    __shared__ int sh[128];
    int tid = threadIdx.x;
    int v = (tid < nb) ? bsum[tid] : 0;
    sh[tid] = v;
    __syncthreads();
#pragma unroll
    for (int o = 1; o < 128; o <<= 1) {
        int t = (tid >= o) ? sh[tid - o] : 0;
        __syncthreads();
        sh[tid] += t;
        __syncthreads();
    }
    if (tid < nb) bsum[tid] = sh[tid] - v;
}

// phase 3: add block offsets; also init cursor and off[n]=E
__global__ void finalize_off_kernel(int* off, int* cur,
                                    const int* __restrict__ bsum, int n, int E) {
    int gid = blockIdx.x * blockDim.x + threadIdx.x;
    if (gid < n) {
        int o = off[gid] + bsum[gid >> 10];
        off[gid] = o;
        cur[gid] = o;
    }
    if (gid == 0) off[n] = E;
}

__global__ void fill_csr_kernel(const int* __restrict__ src,
                                const int* __restrict__ dst,
                                int* cur, int* __restrict__ csr, int E) {
    int e = blockIdx.x * blockDim.x + threadIdx.x;
    if (e >= E) return;
    int d = __ldg(&dst[e]);
    int pos = atomicAdd(&cur[d], 1);
    csr[pos] = __ldg(&src[e]);
}

// ---------------------------------------------------------------------------
// One warp per dst row: gather neighbor rows (4-way unroll -> MLP=4),
// accumulate in regs, write mean.
__global__ void gather_mean_kernel(const float* __restrict__ xsrc,
                                   const int* __restrict__ off,
                                   const int* __restrict__ csr,
                                   float* __restrict__ mean, int M) {
    int row = blockIdx.x * 8 + (threadIdx.x >> 5);
    if (row >= M) return;
    int lane = threadIdx.x & 31;
    int beg = __ldg(&off[row]);
    int end = __ldg(&off[row + 1]);
    float4 a0 = make_float4(0.f, 0.f, 0.f, 0.f);
    float4 a1 = make_float4(0.f, 0.f, 0.f, 0.f);
    float4 a2 = make_float4(0.f, 0.f, 0.f, 0.f);
    float4 a3 = make_float4(0.f, 0.f, 0.f, 0.f);
    int j = beg;
    for (; j + 3 < end; j += 4) {
        int s0 = __ldg(&csr[j + 0]);
        int s1 = __ldg(&csr[j + 1]);
        int s2 = __ldg(&csr[j + 2]);
        int s3 = __ldg(&csr[j + 3]);
        float4 v0 = __ldg(((const float4*)(xsrc + (long)s0 * H)) + lane);
        float4 v1 = __ldg(((const float4*)(xsrc + (long)s1 * H)) + lane);
        float4 v2 = __ldg(((const float4*)(xsrc + (long)s2 * H)) + lane);
        float4 v3 = __ldg(((const float4*)(xsrc + (long)s3 * H)) + lane);
        a0.x += v0.x; a0.y += v0.y; a0.z += v0.z; a0.w += v0.w;
        a1.x += v1.x; a1.y += v1.y; a1.z += v1.z; a1.w += v1.w;
        a2.x += v2.x; a2.y += v2.y; a2.z += v2.z; a2.w += v2.w;
        a3.x += v3.x; a3.y += v3.y; a3.z += v3.z; a3.w += v3.w;
    }
    for (; j < end; ++j) {
        int s0 = __ldg(&csr[j]);
        float4 v0 = __ldg(((const float4*)(xsrc + (long)s0 * H)) + lane);
        a0.x += v0.x; a0.y += v0.y; a0.z += v0.z; a0.w += v0.w;
    }
    float inv = 1.0f / fmaxf((float)(end - beg), 1.0f);
    float4 o;
    o.x = ((a0.x + a1.x) + (a2.x + a3.x)) * inv;
    o.y = ((a0.y + a1.y) + (a2.y + a3.y)) * inv;
    o.z = ((a0.z + a1.z) + (a2.z + a3.z)) * inv;
    o.w = ((a0.w + a1.w) + (a2.w + a3.w)) * inv;
    *(((float4*)(mean + (long)row * H)) + lane) = o;
}

// ---------------------------------------------------------------------------
__device__ __forceinline__ ull ffma2(ull a, ull b, ull c) {
    ull d;
    asm("fma.rn.f32x2 %0, %1, %2, %3;" : "=l"(d) : "l"(a), "l"(b), "l"(c));
    return d;
}

// Fused SAGEConv GEMM + L2-normalize + relu, packed f32x2 FMA, SW pipelined:
// out[m,:] = relu(normalize(mean[m,:] @ Wl + bias + xdst[m,:] @ Wr))
// A = [mean || xdst] (M x 256), B = [Wl ; Wr] (256 x 128)
// Tile 128x128 (full H per block -> row-norm is block-local), 256 threads,
// 8x8 per thread (4 packed col-pairs), K-chunk 16, register prefetch.
__global__ void __launch_bounds__(256, 2)
conv_gemm_kernel(const float* __restrict__ meanA,
                 const float* __restrict__ xdst,
                 const float* __restrict__ wl, const float* __restrict__ wr,
                 const float* __restrict__ bias,
                 float* __restrict__ out, int M) {
    __shared__ float As2[16][256];   // [k][2*m] duplicated pairs (16 KB)
    __shared__ float Bs[16][128];    // [k][j]                    (8 KB)

    int t = threadIdx.x;
    int tcol = t & 15;   // 16 col-groups * 8 cols
    int trow = t >> 4;   // 16 row-groups * 8 rows
    int m0 = blockIdx.x * 128;

    // A-load geometry: idx = t*2+i -> row = idx>>2 (4 float4/row), k4 = idx&3
    const int a_row0 = (t * 2 + 0) >> 2, a_k40 = (t * 2 + 0) & 3;
    const int a_row1 = (t * 2 + 1) >> 2, a_k41 = (t * 2 + 1) & 3;
    // B-load geometry: idx = t*2+i -> krow = idx>>5 (32 float4/krow), c4 = idx&31
    const int b_row0 = (t * 2 + 0) >> 5, b_c40 = (t * 2 + 0) & 31;
    const int b_row1 = (t * 2 + 1) >> 5, b_c41 = (t * 2 + 1) & 31;

    ull acc[8][4];
#pragma unroll
    for (int r = 0; r < 8; ++r)
#pragma unroll
        for (int c = 0; c < 4; ++c) acc[r][c] = 0ull;

    float4 aR0, aR1, bR0, bR1;

    // prefetch chunk 0
    {
        const float* asrc = meanA;
        const float* bsrc = wl;
        int m;
        m = m0 + a_row0;
        aR0 = (m < M) ? *(const float4*)(asrc + (long)m * H + a_k40 * 4)
                      : make_float4(0.f, 0.f, 0.f, 0.f);
        m = m0 + a_row1;
        aR1 = (m < M) ? *(const float4*)(asrc + (long)m * H + a_k41 * 4)
                      : make_float4(0.f, 0.f, 0.f, 0.f);
        bR0 = *(const float4*)(bsrc + (long)b_row0 * H + b_c40 * 4);
        bR1 = *(const float4*)(bsrc + (long)b_row1 * H + b_c41 * 4);
    }

    for (int kc = 0; kc < 16; ++kc) {
        // store current chunk to smem (A duplicated for packed broadcast)
        {
            int kk0 = a_k40 * 4;
            *(float2*)&As2[kk0 + 0][2 * a_row0] = make_float2(aR0.x, aR0.x);
            *(float2*)&As2[kk0 + 1][2 * a_row0] = make_float2(aR0.y, aR0.y);
            *(float2*)&As2[kk0 + 2][2 * a_row0] = make_float2(aR0.z, aR0.z);
            *(float2*)&As2[kk0 + 3][2 * a_row0] = make_float2(aR0.w, aR0.w);
            int kk1 = a_k41 * 4;
            *(float2*)&As2[kk1 + 0][2 * a_row1] = make_float2(aR1.x, aR1.x);
            *(float2*)&As2[kk1 + 1][2 * a_row1] = make_float2(aR1.y, aR1.y);
            *(float2*)&As2[kk1 + 2][2 * a_row1] = make_float2(aR1.z, aR1.z);
            *(float2*)&As2[kk1 + 3][2 * a_row1] = make_float2(aR1.w, aR1.w);
            *(float4*)&Bs[b_row0][b_c40 * 4] = bR0;
            *(float4*)&Bs[b_row1][b_c41 * 4] = bR1;
        }
        __syncthreads();

        // prefetch next chunk (overlaps the FFMA loop below)
        if (kc < 15) {
            int kn = kc + 1;
            const bool mp = (kn < 8);
            const int kbase = (kn & 7) * 16;
            const float* asrc = mp ? meanA : xdst;
            const float* bsrc = mp ? wl : wr;
            int m;
            m = m0 + a_row0;
            aR0 = (m < M) ? *(const float4*)(asrc + (long)m * H + kbase + a_k40 * 4)
                          : make_float4(0.f, 0.f, 0.f, 0.f);
            m = m0 + a_row1;
            aR1 = (m < M) ? *(const float4*)(asrc + (long)m * H + kbase + a_k41 * 4)
                          : make_float4(0.f, 0.f, 0.f, 0.f);
            bR0 = *(const float4*)(bsrc + (long)(kbase + b_row0) * H + b_c40 * 4);
            bR1 = *(const float4*)(bsrc + (long)(kbase + b_row1) * H + b_c41 * 4);
        }

#pragma unroll
        for (int k = 0; k < 16; ++k) {
            const ulonglong2* ap = (const ulonglong2*)&As2[k][trow * 16];
            ulonglong2 A0 = ap[0];
            ulonglong2 A1 = ap[1];
            ulonglong2 A2 = ap[2];
            ulonglong2 A3 = ap[3];
            const ulonglong2* bp = (const ulonglong2*)&Bs[k][tcol * 8];
            ulonglong2 B0 = bp[0];
            ulonglong2 B1 = bp[1];
            ull a[8] = {A0.x, A0.y, A1.x, A1.y, A2.x, A2.y, A3.x, A3.y};
#pragma unroll
            for (int r = 0; r < 8; ++r) {
                acc[r][0] = ffma2(a[r], B0.x, acc[r][0]);
                acc[r][1] = ffma2(a[r], B0.y, acc[r][1]);
                acc[r][2] = ffma2(a[r], B1.x, acc[r][2]);
                acc[r][3] = ffma2(a[r], B1.y, acc[r][3]);
            }
        }
        __syncthreads();
    }

    // ---- epilogue: + bias, row L2-norm (block-local), relu, store ----
    float bv[8];
    {
        float4 f0 = *(const float4*)(bias + tcol * 8);
        float4 f1 = *(const float4*)(bias + tcol * 8 + 4);
        bv[0] = f0.x; bv[1] = f0.y; bv[2] = f0.z; bv[3] = f0.w;
        bv[4] = f1.x; bv[5] = f1.y; bv[6] = f1.z; bv[7] = f1.w;
    }
    float vals[8][8];
#pragma unroll
    for (int r = 0; r < 8; ++r)
#pragma unroll
        for (int c2 = 0; c2 < 4; ++c2) {
            ull p = acc[r][c2];
            vals[r][2 * c2 + 0] = __uint_as_float((unsigned)(p & 0xffffffffull)) + bv[2 * c2 + 0];
            vals[r][2 * c2 + 1] = __uint_as_float((unsigned)(p >> 32)) + bv[2 * c2 + 1];
        }

    // partial sum of squares per (row, tcol) into smem (reuse As2: 128x16 floats)
    float* red = &As2[0][0];
#pragma unroll
    for (int r = 0; r < 8; ++r) {
        float p = 0.f;
#pragma unroll
        for (int c = 0; c < 8; ++c) p = fmaf(vals[r][c], vals[r][c], p);
        red[(trow * 8 + r) * 16 + tcol] = p;
    }
    __syncthreads();

#pragma unroll
    for (int r = 0; r < 8; ++r) {
        int m = m0 + trow * 8 + r;
        const float4* q = (const float4*)&red[(trow * 8 + r) * 16];
        float4 s0 = q[0], s1 = q[1], s2 = q[2], s3 = q[3];
        float s = ((s0.x + s0.y) + (s0.z + s0.w)) + ((s1.x + s1.y) + (s1.z + s1.w))
                + ((s2.x + s2.y) + (s2.z + s2.w)) + ((s3.x + s3.y) + (s3.z + s3.w));
        float scale = 1.0f / fmaxf(sqrtf(s), 1e-12f);
        if (m < M) {
            int j = tcol * 8;
            float4 o;
            o.x = fmaxf(vals[r][0] * scale, 0.f);
            o.y = fmaxf(vals[r][1] * scale, 0.f);
            o.z = fmaxf(vals[r][2] * scale, 0.f);
            o.w = fmaxf(vals[r][3] * scale, 0.f);
            *(float4*)(out + (long)m * H + j) = o;
            o.x = fmaxf(vals[r][4] * scale, 0.f);
            o.y = fmaxf(vals[r][5] * scale, 0.f);
            o.z = fmaxf(vals[r][6] * scale, 0.f);
            o.w = fmaxf(vals[r][7] * scale, 0.f);
            *(float4*)(out + (long)m * H + j + 4) = o;
        }
    }
}

// one warp per labeled edge: dot(xu2[src], xi2[dst])
__global__ void classifier_kernel(const float* __restrict__ xu,
                                  const float* __restrict__ xi,
                                  const int* __restrict__ lsrc,
                                  const int* __restrict__ ldst,
                                  float* __restrict__ out, int L) {
    int e = blockIdx.x * 8 + (threadIdx.x >> 5);
    if (e >= L) return;
    int lane = threadIdx.x & 31;
    int s = __ldg(&lsrc[e]);
    int d = __ldg(&ldst[e]);
    float4 a = __ldg(((const float4*)(xu + (long)s * H)) + lane);
    float4 b = __ldg(((const float4*)(xi + (long)d * H)) + lane);
    float v = a.x * b.x + a.y * b.y + a.z * b.z + a.w * b.w;
#pragma unroll
    for (int o = 16; o; o >>= 1) v += __shfl_xor_sync(0xffffffffu, v, o);
    if (lane == 0) out[e] = v;
}

// ---------------------------------------------------------------------------
extern "C" void kernel_launch(void* const* d_in, const int* in_sizes, int n_in,
                              void* d_out, int out_size) {
    const float* emb_u = (const float*)d_in[0];
    const float* emb_i = (const float*)d_in[1];
    const int* er  = (const int*)d_in[2];   // edge_rates [2, E]
    const int* erv = (const int*)d_in[3];   // edge_rev   [2, E]
    const int* lbl = (const int*)d_in[4];   // edge_label_index [2, L]
    const float* w1l_rates = (const float*)d_in[5];
    const float* w1r_rates = (const float*)d_in[6];
    const float* w1l_rev   = (const float*)d_in[7];
    const float* w1r_rev   = (const float*)d_in[8];
    const float* w2l_rates = (const float*)d_in[9];
    const float* w2r_rates = (const float*)d_in[10];
    const float* w2l_rev   = (const float*)d_in[11];
    const float* w2r_rev   = (const float*)d_in[12];
    const float* b1_rates  = (const float*)d_in[13];
    const float* b1_rev    = (const float*)d_in[14];
    const float* b2_rates  = (const float*)d_in[15];
    const float* b2_rev    = (const float*)d_in[16];
    float* out = (float*)d_out;

    const int E = in_sizes[2] / 2;
    const int L = in_sizes[4] / 2;

    float *mean, *xi1, *xu1, *xi2, *xu2;
    int *cnt, *off, *cur, *csr, *bsum;
    cudaGetSymbolAddress((void**)&mean, g_mean);
    cudaGetSymbolAddress((void**)&xi1,  g_xi1);
    cudaGetSymbolAddress((void**)&xu1,  g_xu1);
    cudaGetSymbolAddress((void**)&xi2,  g_xi2);
    cudaGetSymbolAddress((void**)&xu2,  g_xu2);
    cudaGetSymbolAddress((void**)&cnt,  g_cnt);
    cudaGetSymbolAddress((void**)&off,  g_off);
    cudaGetSymbolAddress((void**)&cur,  g_cur);
    cudaGetSymbolAddress((void**)&csr,  g_csr);
    cudaGetSymbolAddress((void**)&bsum, g_bsum);

    // index 0 = rates (dst = items), index 1 = rev (dst = users)
    int* cnt_t[2]  = {cnt, cnt + NNODE};
    int* off_t[2]  = {off, off + (NNODE + 1)};
    int* cur_t[2]  = {cur, cur + NNODE};
    int* csr_t[2]  = {csr, csr + EMAX};
    int* bsum_t[2] = {bsum, bsum + SCAN_NB};
    const int* src_t[2] = {er, erv};
    const int* dst_t[2] = {er + E, erv + E};

    const int NB_E    = (E + 255) / 256;
    const int NB_GEMM = (NNODE + 127) / 128;
    const int NB_ROWS = (NNODE + 7) / 8;
    const int NB_L    = (L + 7) / 8;
    const int NB_N    = (NNODE + 255) / 256;

    // ---- CSR build type 0, first 3 launches ----
    zero_int4_kernel<<<(NNODE / 4 + 255) / 256, 256>>>((int4*)cnt_t[0], NNODE / 4);      // 1
    count_kernel<<<NB_E, 256>>>(dst_t[0], cnt_t[0], E);                                  // 2
    scan_block_kernel<<<SCAN_NB, SCAN_BS>>>(cnt_t[0], off_t[0], bsum_t[0], NNODE);       // 3

    // ---- DIAGNOSTIC: dummy conv as the 4th launch (the one ncu captures).
    // Reads stale g_mean (deterministic output is unaffected: writes xi2,
    // which conv D overwrites below). Costs one conv pass; buys the first
    // real profile of the hot GEMM.
    conv_gemm_kernel<<<NB_GEMM, 256>>>(mean, emb_i, w1l_rates, w1r_rates,
                                       b1_rates, xi2, NNODE);                            // 4 (profiled)

    // ---- finish CSR build type 0 ----
    scan_sums_kernel<<<1, 128>>>(bsum_t[0], SCAN_NB);                                    // 5
    finalize_off_kernel<<<NB_N, 256>>>(off_t[0], cur_t[0], bsum_t[0], NNODE, E);         // 6
    fill_csr_kernel<<<NB_E, 256>>>(src_t[0], dst_t[0], cur_t[0], csr_t[0], E);           // 7

    // ---- CSR build type 1 ----
    zero_int4_kernel<<<(NNODE / 4 + 255) / 256, 256>>>((int4*)cnt_t[1], NNODE / 4);
    count_kernel<<<NB_E, 256>>>(dst_t[1], cnt_t[1], E);
    scan_block_kernel<<<SCAN_NB, SCAN_BS>>>(cnt_t[1], off_t[1], bsum_t[1], NNODE);
    scan_sums_kernel<<<1, 128>>>(bsum_t[1], SCAN_NB);
    finalize_off_kernel<<<NB_N, 256>>>(off_t[1], cur_t[1], bsum_t[1], NNODE, E);
    fill_csr_kernel<<<NB_E, 256>>>(src_t[1], dst_t[1], cur_t[1], csr_t[1], E);

    // ---- layer 1: items <- users over edge_rates ----
    gather_mean_kernel<<<NB_ROWS, 256>>>(emb_u, off_t[0], csr_t[0], mean, NNODE);
    conv_gemm_kernel<<<NB_GEMM, 256>>>(mean, emb_i, w1l_rates, w1r_rates,
                                       b1_rates, xi1, NNODE);

    // ---- layer 1: users <- items over edge_rev ----
    gather_mean_kernel<<<NB_ROWS, 256>>>(emb_i, off_t[1], csr_t[1], mean, NNODE);
    conv_gemm_kernel<<<NB_GEMM, 256>>>(mean, emb_u, w1l_rev, w1r_rev,
                                       b1_rev, xu1, NNODE);

    // ---- layer 2: items <- users ----
    gather_mean_kernel<<<NB_ROWS, 256>>>(xu1, off_t[0], csr_t[0], mean, NNODE);
    conv_gemm_kernel<<<NB_GEMM, 256>>>(mean, xi1, w2l_rates, w2r_rates,
                                       b2_rates, xi2, NNODE);

    // ---- layer 2: users <- items ----
    gather_mean_kernel<<<NB_ROWS, 256>>>(xi1, off_t[1], csr_t[1], mean, NNODE);
    conv_gemm_kernel<<<NB_GEMM, 256>>>(mean, xu1, w2l_rev, w2r_rev,
                                       b2_rev, xu2, NNODE);

    // ---- classifier ----
    classifier_kernel<<<NB_L, 256>>>(xu2, xi2, lbl, lbl + L, out, L);
}

// round 16
// speedup vs baseline: 1.3667x; 1.3261x over previous
#include <cuda_runtime.h>

#define H 128
#define NNODE 100000
#define EMAX 1600000
#define SCAN_BS 1024
#define SCAN_NB ((NNODE + SCAN_BS - 1) / SCAN_BS)   // 98

typedef unsigned long long ull;

// ---- scratch (device globals: no allocation allowed) ----
__device__ float g_mean[NNODE * H];
__device__ float g_xi1[NNODE * H];
__device__ float g_xu1[NNODE * H];
__device__ float g_xi2[NNODE * H];
__device__ float g_xu2[NNODE * H];
__device__ int g_cnt[2][NNODE];
__device__ int g_off[2][NNODE + 1];
__device__ int g_cur[2][NNODE];
__device__ int g_csr[2][EMAX];
__device__ int g_bsum[2][SCAN_NB];

// ---------------------------------------------------------------------------
__global__ void zero_int4_kernel(int4* p, int n4) {
    int i = blockIdx.x * blockDim.x + threadIdx.x;
    if (i < n4) p[i] = make_int4(0, 0, 0, 0);
}

__global__ void count_kernel(const int* __restrict__ dst, int* cnt, int E) {
    int i = blockIdx.x * blockDim.x + threadIdx.x;
    if (i < E) atomicAdd(&cnt[dst[i]], 1);
}

// phase 1: per-block exclusive scan, emit block sums
__global__ void scan_block_kernel(const int* __restrict__ cnt, int* off,
                                  int* bsum, int n) {
    __shared__ int sh[SCAN_BS];
    int tid = threadIdx.x;
    int gid = blockIdx.x * SCAN_BS + tid;
    int v = (gid < n) ? cnt[gid] : 0;
    sh[tid] = v;
    __syncthreads();
#pragma unroll
    for (int o = 1; o < SCAN_BS; o <<= 1) {
        int t = (tid >= o) ? sh[tid - o] : 0;
        __syncthreads();
        sh[tid] += t;
        __syncthreads();
    }
    if (gid < n) off[gid] = sh[tid] - v;   // exclusive
    if (tid == SCAN_BS - 1) bsum[blockIdx.x] = sh[tid];
}

// phase 2: single-block exclusive scan of block sums (nb <= 128)
__global__ void scan_sums_kernel(int* bsum, int nb) {
    __shared__ int sh[128];
    int tid = threadIdx.x;
    int v = (tid < nb) ? bsum[tid] : 0;
    sh[tid] = v;
    __syncthreads();
#pragma unroll
    for (int o = 1; o < 128; o <<= 1) {
        int t = (tid >= o) ? sh[tid - o] : 0;
        __syncthreads();
        sh[tid] += t;
        __syncthreads();
    }
    if (tid < nb) bsum[tid] = sh[tid] - v;
}

// phase 3: add block offsets; also init cursor and off[n]=E
__global__ void finalize_off_kernel(int* off, int* cur,
                                    const int* __restrict__ bsum, int n, int E) {
    int gid = blockIdx.x * blockDim.x + threadIdx.x;
    if (gid < n) {
        int o = off[gid] + bsum[gid >> 10];
        off[gid] = o;
        cur[gid] = o;
    }
    if (gid == 0) off[n] = E;
}

__global__ void fill_csr_kernel(const int* __restrict__ src,
                                const int* __restrict__ dst,
                                int* cur, int* __restrict__ csr, int E) {
    int e = blockIdx.x * blockDim.x + threadIdx.x;
    if (e >= E) return;
    int d = __ldg(&dst[e]);
    int pos = atomicAdd(&cur[d], 1);
    csr[pos] = __ldg(&src[e]);
}

// ---------------------------------------------------------------------------
// One warp per dst row: gather neighbor rows (4-way unroll -> MLP=4),
// accumulate in regs, write mean.
__global__ void gather_mean_kernel(const float* __restrict__ xsrc,
                                   const int* __restrict__ off,
                                   const int* __restrict__ csr,
                                   float* __restrict__ mean, int M) {
    int row = blockIdx.x * 8 + (threadIdx.x >> 5);
    if (row >= M) return;
    int lane = threadIdx.x & 31;
    int beg = __ldg(&off[row]);
    int end = __ldg(&off[row + 1]);
    float4 a0 = make_float4(0.f, 0.f, 0.f, 0.f);
    float4 a1 = make_float4(0.f, 0.f, 0.f, 0.f);
    float4 a2 = make_float4(0.f, 0.f, 0.f, 0.f);
    float4 a3 = make_float4(0.f, 0.f, 0.f, 0.f);
    int j = beg;
    for (; j + 3 < end; j += 4) {
        int s0 = __ldg(&csr[j + 0]);
        int s1 = __ldg(&csr[j + 1]);
        int s2 = __ldg(&csr[j + 2]);
        int s3 = __ldg(&csr[j + 3]);
        float4 v0 = __ldg(((const float4*)(xsrc + (long)s0 * H)) + lane);
        float4 v1 = __ldg(((const float4*)(xsrc + (long)s1 * H)) + lane);
        float4 v2 = __ldg(((const float4*)(xsrc + (long)s2 * H)) + lane);
        float4 v3 = __ldg(((const float4*)(xsrc + (long)s3 * H)) + lane);
        a0.x += v0.x; a0.y += v0.y; a0.z += v0.z; a0.w += v0.w;
        a1.x += v1.x; a1.y += v1.y; a1.z += v1.z; a1.w += v1.w;
        a2.x += v2.x; a2.y += v2.y; a2.z += v2.z; a2.w += v2.w;
        a3.x += v3.x; a3.y += v3.y; a3.z += v3.z; a3.w += v3.w;
    }
    for (; j < end; ++j) {
        int s0 = __ldg(&csr[j]);
        float4 v0 = __ldg(((const float4*)(xsrc + (long)s0 * H)) + lane);
        a0.x += v0.x; a0.y += v0.y; a0.z += v0.z; a0.w += v0.w;
    }
    float inv = 1.0f / fmaxf((float)(end - beg), 1.0f);
    float4 o;
    o.x = ((a0.x + a1.x) + (a2.x + a3.x)) * inv;
    o.y = ((a0.y + a1.y) + (a2.y + a3.y)) * inv;
    o.z = ((a0.z + a1.z) + (a2.z + a3.z)) * inv;
    o.w = ((a0.w + a1.w) + (a2.w + a3.w)) * inv;
    *(((float4*)(mean + (long)row * H)) + lane) = o;
}

// ---------------------------------------------------------------------------
__device__ __forceinline__ ull ffma2(ull a, ull b, ull c) {
    ull d;
    asm("fma.rn.f32x2 %0, %1, %2, %3;" : "=l"(d) : "l"(a), "l"(b), "l"(c));
    return d;
}

// duplicate one f32 into a packed f32x2 (single mov.b64, ALU pipe)
__device__ __forceinline__ ull dup2(float x) {
    ull d;
    asm("mov.b64 %0, {%1, %1};" : "=l"(d) : "f"(x));
    return d;
}

// Fused SAGEConv GEMM + L2-normalize + relu, packed f32x2 FMA.
// out[m,:] = relu(normalize(mean[m,:] @ Wl + bias + xdst[m,:] @ Wr))
// A = [mean || xdst] (M x 256), B = [Wl ; Wr] (256 x 128)
// Tile 128x128, 256 threads, 8x8 per thread (4 packed col-pairs), K-chunk 16.
// A tile stored PLAIN [k][m] (no duplication) — broadcast pairs {a,a} are
// built in registers via mov.b64, cutting LDS wavefronts 8->6 per warp-k
// and halving A's STS traffic (ncu R14: L1 79% vs fma 42% — LDS-bound).
__global__ void __launch_bounds__(256, 2)
conv_gemm_kernel(const float* __restrict__ meanA,
                 const float* __restrict__ xdst,
                 const float* __restrict__ wl, const float* __restrict__ wr,
                 const float* __restrict__ bias,
                 float* __restrict__ out, int M) {
    __shared__ float As[16][128];   // [k][m] plain (8 KB)
    __shared__ float Bs[16][128];   // [k][j]       (8 KB)

    int t = threadIdx.x;
    int tcol = t & 15;   // 16 col-groups * 8 cols
    int trow = t >> 4;   // 16 row-groups * 8 rows
    int m0 = blockIdx.x * 128;

    // A-load geometry: idx = t*2+i -> row = idx>>2 (4 float4/row), k4 = idx&3
    const int a_row0 = (t * 2 + 0) >> 2, a_k40 = (t * 2 + 0) & 3;
    const int a_row1 = (t * 2 + 1) >> 2, a_k41 = (t * 2 + 1) & 3;
    // B-load geometry: idx = t*2+i -> krow = idx>>5 (32 float4/krow), c4 = idx&31
    const int b_row0 = (t * 2 + 0) >> 5, b_c40 = (t * 2 + 0) & 31;
    const int b_row1 = (t * 2 + 1) >> 5, b_c41 = (t * 2 + 1) & 31;

    ull acc[8][4];
#pragma unroll
    for (int r = 0; r < 8; ++r)
#pragma unroll
        for (int c = 0; c < 4; ++c) acc[r][c] = 0ull;

    float4 aR0, aR1, bR0, bR1;

    // prefetch chunk 0
    {
        int m;
        m = m0 + a_row0;
        aR0 = (m < M) ? *(const float4*)(meanA + (long)m * H + a_k40 * 4)
                      : make_float4(0.f, 0.f, 0.f, 0.f);
        m = m0 + a_row1;
        aR1 = (m < M) ? *(const float4*)(meanA + (long)m * H + a_k41 * 4)
                      : make_float4(0.f, 0.f, 0.f, 0.f);
        bR0 = *(const float4*)(wl + (long)b_row0 * H + b_c40 * 4);
        bR1 = *(const float4*)(wl + (long)b_row1 * H + b_c41 * 4);
    }

    for (int kc = 0; kc < 16; ++kc) {
        // store current chunk to smem (A plain: 4 STS.32 per float4)
        {
            int kk0 = a_k40 * 4;
            As[kk0 + 0][a_row0] = aR0.x;
            As[kk0 + 1][a_row0] = aR0.y;
            As[kk0 + 2][a_row0] = aR0.z;
            As[kk0 + 3][a_row0] = aR0.w;
            int kk1 = a_k41 * 4;
            As[kk1 + 0][a_row1] = aR1.x;
            As[kk1 + 1][a_row1] = aR1.y;
            As[kk1 + 2][a_row1] = aR1.z;
            As[kk1 + 3][a_row1] = aR1.w;
            *(float4*)&Bs[b_row0][b_c40 * 4] = bR0;
            *(float4*)&Bs[b_row1][b_c41 * 4] = bR1;
        }
        __syncthreads();

        // prefetch next chunk (overlaps the FFMA loop below)
        if (kc < 15) {
            int kn = kc + 1;
            const bool mp = (kn < 8);
            const int kbase = (kn & 7) * 16;
            const float* asrc = mp ? meanA : xdst;
            const float* bsrc = mp ? wl : wr;
            int m;
            m = m0 + a_row0;
            aR0 = (m < M) ? *(const float4*)(asrc + (long)m * H + kbase + a_k40 * 4)
                          : make_float4(0.f, 0.f, 0.f, 0.f);
            m = m0 + a_row1;
            aR1 = (m < M) ? *(const float4*)(asrc + (long)m * H + kbase + a_k41 * 4)
                          : make_float4(0.f, 0.f, 0.f, 0.f);
            bR0 = *(const float4*)(bsrc + (long)(kbase + b_row0) * H + b_c40 * 4);
            bR1 = *(const float4*)(bsrc + (long)(kbase + b_row1) * H + b_c41 * 4);
        }

#pragma unroll
        for (int k = 0; k < 16; ++k) {
            const float4* ap = (const float4*)&As[k][trow * 8];
            float4 A0 = ap[0];
            float4 A1 = ap[1];
            const ulonglong2* bp = (const ulonglong2*)&Bs[k][tcol * 8];
            ulonglong2 B0 = bp[0];
            ulonglong2 B1 = bp[1];
            ull a[8];
            a[0] = dup2(A0.x); a[1] = dup2(A0.y);
            a[2] = dup2(A0.z); a[3] = dup2(A0.w);
            a[4] = dup2(A1.x); a[5] = dup2(A1.y);
            a[6] = dup2(A1.z); a[7] = dup2(A1.w);
#pragma unroll
            for (int r = 0; r < 8; ++r) {
                acc[r][0] = ffma2(a[r], B0.x, acc[r][0]);
                acc[r][1] = ffma2(a[r], B0.y, acc[r][1]);
                acc[r][2] = ffma2(a[r], B1.x, acc[r][2]);
                acc[r][3] = ffma2(a[r], B1.y, acc[r][3]);
            }
        }
        __syncthreads();
    }

    // ---- epilogue: + bias, row L2-norm (block-local), relu, store ----
    float bv[8];
    {
        float4 f0 = *(const float4*)(bias + tcol * 8);
        float4 f1 = *(const float4*)(bias + tcol * 8 + 4);
        bv[0] = f0.x; bv[1] = f0.y; bv[2] = f0.z; bv[3] = f0.w;
        bv[4] = f1.x; bv[5] = f1.y; bv[6] = f1.z; bv[7] = f1.w;
    }
    float vals[8][8];
#pragma unroll
    for (int r = 0; r < 8; ++r)
#pragma unroll
        for (int c2 = 0; c2 < 4; ++c2) {
            ull p = acc[r][c2];
            vals[r][2 * c2 + 0] = __uint_as_float((unsigned)(p & 0xffffffffull)) + bv[2 * c2 + 0];
            vals[r][2 * c2 + 1] = __uint_as_float((unsigned)(p >> 32)) + bv[2 * c2 + 1];
        }

    // partial sum of squares per (row, tcol) into smem (reuse As: 128x16 floats)
    float* red = &As[0][0];
#pragma unroll
    for (int r = 0; r < 8; ++r) {
        float p = 0.f;
#pragma unroll
        for (int c = 0; c < 8; ++c) p = fmaf(vals[r][c], vals[r][c], p);
        red[(trow * 8 + r) * 16 + tcol] = p;
    }
    __syncthreads();

#pragma unroll
    for (int r = 0; r < 8; ++r) {
        int m = m0 + trow * 8 + r;
        const float4* q = (const float4*)&red[(trow * 8 + r) * 16];
        float4 s0 = q[0], s1 = q[1], s2 = q[2], s3 = q[3];
        float s = ((s0.x + s0.y) + (s0.z + s0.w)) + ((s1.x + s1.y) + (s1.z + s1.w))
                + ((s2.x + s2.y) + (s2.z + s2.w)) + ((s3.x + s3.y) + (s3.z + s3.w));
        float scale = 1.0f / fmaxf(sqrtf(s), 1e-12f);
        if (m < M) {
            int j = tcol * 8;
            float4 o;
            o.x = fmaxf(vals[r][0] * scale, 0.f);
            o.y = fmaxf(vals[r][1] * scale, 0.f);
            o.z = fmaxf(vals[r][2] * scale, 0.f);
            o.w = fmaxf(vals[r][3] * scale, 0.f);
            *(float4*)(out + (long)m * H + j) = o;
            o.x = fmaxf(vals[r][4] * scale, 0.f);
            o.y = fmaxf(vals[r][5] * scale, 0.f);
            o.z = fmaxf(vals[r][6] * scale, 0.f);
            o.w = fmaxf(vals[r][7] * scale, 0.f);
            *(float4*)(out + (long)m * H + j + 4) = o;
        }
    }
}

// one warp per labeled edge: dot(xu2[src], xi2[dst])
__global__ void classifier_kernel(const float* __restrict__ xu,
                                  const float* __restrict__ xi,
                                  const int* __restrict__ lsrc,
                                  const int* __restrict__ ldst,
                                  float* __restrict__ out, int L) {
    int e = blockIdx.x * 8 + (threadIdx.x >> 5);
    if (e >= L) return;
    int lane = threadIdx.x & 31;
    int s = __ldg(&lsrc[e]);
    int d = __ldg(&ldst[e]);
    float4 a = __ldg(((const float4*)(xu + (long)s * H)) + lane);
    float4 b = __ldg(((const float4*)(xi + (long)d * H)) + lane);
    float v = a.x * b.x + a.y * b.y + a.z * b.z + a.w * b.w;
#pragma unroll
    for (int o = 16; o; o >>= 1) v += __shfl_xor_sync(0xffffffffu, v, o);
    if (lane == 0) out[e] = v;
}

// ---------------------------------------------------------------------------
extern "C" void kernel_launch(void* const* d_in, const int* in_sizes, int n_in,
                              void* d_out, int out_size) {
    const float* emb_u = (const float*)d_in[0];
    const float* emb_i = (const float*)d_in[1];
    const int* er  = (const int*)d_in[2];   // edge_rates [2, E]
    const int* erv = (const int*)d_in[3];   // edge_rev   [2, E]
    const int* lbl = (const int*)d_in[4];   // edge_label_index [2, L]
    const float* w1l_rates = (const float*)d_in[5];
    const float* w1r_rates = (const float*)d_in[6];
    const float* w1l_rev   = (const float*)d_in[7];
    const float* w1r_rev   = (const float*)d_in[8];
    const float* w2l_rates = (const float*)d_in[9];
    const float* w2r_rates = (const float*)d_in[10];
    const float* w2l_rev   = (const float*)d_in[11];
    const float* w2r_rev   = (const float*)d_in[12];
    const float* b1_rates  = (const float*)d_in[13];
    const float* b1_rev    = (const float*)d_in[14];
    const float* b2_rates  = (const float*)d_in[15];
    const float* b2_rev    = (const float*)d_in[16];
    float* out = (float*)d_out;

    const int E = in_sizes[2] / 2;
    const int L = in_sizes[4] / 2;

    float *mean, *xi1, *xu1, *xi2, *xu2;
    int *cnt, *off, *cur, *csr, *bsum;
    cudaGetSymbolAddress((void**)&mean, g_mean);
    cudaGetSymbolAddress((void**)&xi1,  g_xi1);
    cudaGetSymbolAddress((void**)&xu1,  g_xu1);
    cudaGetSymbolAddress((void**)&xi2,  g_xi2);
    cudaGetSymbolAddress((void**)&xu2,  g_xu2);
    cudaGetSymbolAddress((void**)&cnt,  g_cnt);
    cudaGetSymbolAddress((void**)&off,  g_off);
    cudaGetSymbolAddress((void**)&cur,  g_cur);
    cudaGetSymbolAddress((void**)&csr,  g_csr);
    cudaGetSymbolAddress((void**)&bsum, g_bsum);

    // index 0 = rates (dst = items), index 1 = rev (dst = users)
    int* cnt_t[2]  = {cnt, cnt + NNODE};
    int* off_t[2]  = {off, off + (NNODE + 1)};
    int* cur_t[2]  = {cur, cur + NNODE};
    int* csr_t[2]  = {csr, csr + EMAX};
    int* bsum_t[2] = {bsum, bsum + SCAN_NB};
    const int* src_t[2] = {er, erv};
    const int* dst_t[2] = {er + E, erv + E};

    const int NB_E    = (E + 255) / 256;
    const int NB_GEMM = (NNODE + 127) / 128;
    const int NB_ROWS = (NNODE + 7) / 8;
    const int NB_L    = (L + 7) / 8;
    const int NB_N    = (NNODE + 255) / 256;

    // ---- CSR build (both edge types, reused by both layers) ----
    for (int ty = 0; ty < 2; ++ty) {
        zero_int4_kernel<<<(NNODE / 4 + 255) / 256, 256>>>((int4*)cnt_t[ty], NNODE / 4);
        count_kernel<<<NB_E, 256>>>(dst_t[ty], cnt_t[ty], E);
        scan_block_kernel<<<SCAN_NB, SCAN_BS>>>(cnt_t[ty], off_t[ty], bsum_t[ty], NNODE);
        scan_sums_kernel<<<1, 128>>>(bsum_t[ty], SCAN_NB);
        finalize_off_kernel<<<NB_N, 256>>>(off_t[ty], cur_t[ty], bsum_t[ty], NNODE, E);
        fill_csr_kernel<<<NB_E, 256>>>(src_t[ty], dst_t[ty], cur_t[ty], csr_t[ty], E);
    }

    // ---- layer 1: items <- users over edge_rates ----
    gather_mean_kernel<<<NB_ROWS, 256>>>(emb_u, off_t[0], csr_t[0], mean, NNODE);
    conv_gemm_kernel<<<NB_GEMM, 256>>>(mean, emb_i, w1l_rates, w1r_rates,
                                       b1_rates, xi1, NNODE);

    // ---- layer 1: users <- items over edge_rev ----
    gather_mean_kernel<<<NB_ROWS, 256>>>(emb_i, off_t[1], csr_t[1], mean, NNODE);
    conv_gemm_kernel<<<NB_GEMM, 256>>>(mean, emb_u, w1l_rev, w1r_rev,
                                       b1_rev, xu1, NNODE);

    // ---- layer 2: items <- users ----
    gather_mean_kernel<<<NB_ROWS, 256>>>(xu1, off_t[0], csr_t[0], mean, NNODE);
    conv_gemm_kernel<<<NB_GEMM, 256>>>(mean, xi1, w2l_rates, w2r_rates,
                                       b2_rates, xi2, NNODE);

    // ---- layer 2: users <- items ----
    gather_mean_kernel<<<NB_ROWS, 256>>>(xi1, off_t[1], csr_t[1], mean, NNODE);
    conv_gemm_kernel<<<NB_GEMM, 256>>>(mean, xu1, w2l_rev, w2r_rev,
                                       b2_rev, xu2, NNODE);

    // ---- classifier ----
    classifier_kernel<<<NB_L, 256>>>(xu2, xi2, lbl, lbl + L, out, L);
}